// round 14
// baseline (speedup 1.0000x reference)
#include <cuda_runtime.h>

#define LAM 0.95f

// Lambda-return reverse scan.
// acc = reward[i] + discount[i] * (LAM*acc + (1-LAM)*value[i+1]),  i = T-2 .. 0
//
// FINAL champion config (all axes single-variable tested, R1-R13):
//  - reward (32MB): __ldlu  — read once per replay, never retained in L2.
//  - value+discount (64MB): __ldg — retained in L2, hit every replay.
//  - outputs (31MB): __stcs — evict-first, write-combined, lazy writeback.
//  - float2/thread, 64-thread blocks (4096 CTAs), D=5 software pipeline.
//  - Within each refill, L2-hitting __ldg loads are issued BEFORE the
//    DRAM-missing __ldlu (L1tex wavefront queue is issue-order FIFO; short
//    latency first unblocks consumers sooner).
// Steady state is LTS-bound: 127MB mandatory L2 traffic @ ~8.8TB/s cap
// -> ~14.4us floor; this kernel runs at ~97% of it.
template <int T>
__global__ void __launch_bounds__(64)
lambda_return_kernel(const float2* __restrict__ reward,
                     const float2* __restrict__ value,
                     const float2* __restrict__ discount,
                     float2* __restrict__ out,
                     int B2)
{
    const int b = blockIdx.x * blockDim.x + threadIdx.x;
    if (b >= B2) return;

    constexpr int S = T - 1;           // scan steps, i = S-1 .. 0
    constexpr int D = 5;               // pipeline depth

    float2 r[D], d[D], v[D];

    // Prologue: L2-hitting loads first, streaming miss last.
#pragma unroll
    for (int k = 0; k < D; ++k) {
        const int i = S - 1 - k;
        d[k] = __ldg(&discount[i * B2 + b]);    // retain (L2 hit)
        v[k] = __ldg(&value[(i + 1) * B2 + b]); // retain (L2 hit)
        r[k] = __ldlu(&reward[i * B2 + b]);     // stream (DRAM miss)
    }

    // bootstrap = value[T-1] == step S-1's v_next (slot 0).
    float2 acc = v[0];

#pragma unroll
    for (int i = S - 1; i >= 0; --i) {
        const int k = (S - 1 - i) % D;
        const float2 rr = r[k];
        const float2 dd = d[k];
        const float2 vv = v[k];

        if (i - D >= 0) {
            const int j = i - D;
            d[k] = __ldg(&discount[j * B2 + b]);
            v[k] = __ldg(&value[(j + 1) * B2 + b]);
            r[k] = __ldlu(&reward[j * B2 + b]);
        }

        acc.x = fmaf(dd.x, fmaf(LAM, acc.x, (1.0f - LAM) * vv.x), rr.x);
        acc.y = fmaf(dd.y, fmaf(LAM, acc.y, (1.0f - LAM) * vv.y), rr.y);

        // Evict-first store: outputs never re-read.
        __stcs(&out[i * B2 + b], acc);
    }
}

// Generic runtime-T fallback (same math, same policies).
__global__ void lambda_return_kernel_gen(const float2* __restrict__ reward,
                                         const float2* __restrict__ value,
                                         const float2* __restrict__ discount,
                                         float2* __restrict__ out,
                                         int B2, int T)
{
    const int b = blockIdx.x * blockDim.x + threadIdx.x;
    if (b >= B2) return;

    float2 acc = value[(T - 1) * B2 + b];

    for (int i = T - 2; i >= 0; --i) {
        float2 d  = __ldg(&discount[i * B2 + b]);
        float2 vn = __ldg(&value[(i + 1) * B2 + b]);
        float2 r  = __ldlu(&reward[i * B2 + b]);

        acc.x = fmaf(d.x, fmaf(LAM, acc.x, (1.0f - LAM) * vn.x), r.x);
        acc.y = fmaf(d.y, fmaf(LAM, acc.y, (1.0f - LAM) * vn.y), r.y);

        __stcs(&out[i * B2 + b], acc);
    }
}

extern "C" void kernel_launch(void* const* d_in, const int* in_sizes, int n_in,
                              void* d_out, int out_size)
{
    // Inputs in metadata order: reward [T,B], value [T,B], discount [T,B].
    const float* reward   = (const float*)d_in[0];
    const float* value    = (const float*)d_in[1];
    const float* discount = (const float*)d_in[2];
    float* out = (float*)d_out;

    // total = T*B, out_size = (T-1)*B  =>  B = total - out_size
    const int total = in_sizes[0];
    const int B = total - out_size;
    const int T = total / B;

    const int B2 = B / 2;
    const int threads = 64;
    const int blocks = (B2 + threads - 1) / threads;

    if (T == 16) {
        lambda_return_kernel<16><<<blocks, threads>>>(
            (const float2*)reward, (const float2*)value, (const float2*)discount,
            (float2*)out, B2);
    } else {
        lambda_return_kernel_gen<<<blocks, threads>>>(
            (const float2*)reward, (const float2*)value, (const float2*)discount,
            (float2*)out, B2, T);
    }
}